// round 15
// baseline (speedup 1.0000x reference)
#include <cuda_runtime.h>

// Shapes fixed by the dataset: u (B=64, L=8192), ev (K=32, L), lam (K)
#define L      8192
#define NB     64
#define NK     32
#define HALF   4096   // L/2
#define KD     2048   // number of odd d < L/2
#define NBLK   384    // all co-resident: 3 blocks/SM capacity (444) >= 384

// Device scratch (no allocs allowed)
__device__ float g_ct2[KD];      // (2/L)*cot(pi*(2k+1)/L)
__device__ float g_P[L];         // P[l] = sum_k lam_k ev[k][l]
__device__ float g_Po[HALF];     // P at odd l
__device__ float g_Pe[HALF];     // P at even l
__device__ float g_pa4[256];     // quarter-row Re partials
__device__ float g_pc4[256];     // quarter-row Im partials
__device__ float g_Qp[3][L];     // Q partials per k-split
__device__ int   g_cnt;          // grid-barrier epoch counter (2 barriers/launch)

// ---------------------------------------------------------------------------
// Fused persistent kernel: 384 blocks x 512 threads, all resident (3/SM cap).
// Phase 1: blocks [0,256): a/c quarter-row partials (b=bx>>2, q=bx&3).
//          blocks [256,384): P chunk of 64 l's (k-parallel park + reduce),
//          plus a 16-entry g_ct2 chunk.
// Barrier. Phase 2: block (h = bx>>7 k-split, p, m0): partial
//   Q over k in [K0, K0+KC) for 64 l's -> g_Qp[h].  KC = 640/768/640.
// Barrier. Phase 3: fully-coalesced combine out = a*P + c*(q0+q1+q2).
__global__ void __launch_bounds__(512, 3) kfused(const float* __restrict__ u,
                                                 const float* __restrict__ ev,
                                                 const float* __restrict__ lam,
                                                 float* __restrict__ out) {
    // Overlaid smem: phase 1 uses SM[0..2047] as PS; phase 2 uses the regions.
    __shared__ alignas(16) float SM[3564];
    float* SA   = SM;            // phase2: KC+64 <= 832  (pad to 848)
    float* SB   = SM + 848;      // phase2: KC+64 <= 832  (pad to 848)
    float* CTs  = SM + 1696;     // phase2: KC <= 768
    float* red2 = SM + 2464;     // 16*68 = 1088
    __shared__ float wa[16], wc[16];

    const int t  = threadIdx.x;
    const int bx = blockIdx.x;

    // ======================= Phase 1 =======================
    if (bx < 256) {
        // ---- a/c quarter-row partial: b = bx>>2, quarter = bx&3 ----
        const int b = bx >> 2;
        const int i = (bx & 3) * 512 + t;          // float4 index (2048/row)
        float4 uv = ((const float4*)(u + (size_t)b * L))[i];
        float x1 = (float)(4 * i + 1) * (1.0f / (float)L);
        float x3 = (float)(4 * i + 3) * (1.0f / (float)L);
        float c1 = __fdividef(cospif(x1), sinpif(x1));
        float c3 = __fdividef(cospif(x3), sinpif(x3));
        float a = uv.x + uv.z;
        float c = -(uv.y * c1 + uv.w * c3);
        if (i == 0) a += (float)(L / 2) * uv.x;
#pragma unroll
        for (int off = 16; off > 0; off >>= 1) {
            a += __shfl_down_sync(0xffffffffu, a, off);
            c += __shfl_down_sync(0xffffffffu, c, off);
        }
        if ((t & 31) == 0) { wa[t >> 5] = a; wc[t >> 5] = c; }
        __syncthreads();
        if (t == 0) {
            float av = 0.0f, cv = 0.0f;
#pragma unroll
            for (int w2 = 0; w2 < 16; w2++) { av += wa[w2]; cv += wc[w2]; }
            g_pa4[bx] = av; g_pc4[bx] = cv;
        }
    } else {
        // ---- P chunk: 64 l's at [pb*64, pb*64+64) ----
        const int pb = bx - 256;                   // 0..127
        const int k  = t >> 4;                     // 0..31
        const int lo = t & 15;                     // 0..15
        float4 e4 = ((const float4*)ev)[k * (L / 4) + pb * 16 + lo];
        float lk = __ldg(lam + k);
        float4 v; v.x = lk * e4.x; v.y = lk * e4.y; v.z = lk * e4.z; v.w = lk * e4.w;
        ((float4*)SM)[k * 16 + lo] = v;            // PS[k*64 + 4*lo + comp]
        if (t < 16) {
            int idx = pb * 16 + t;                 // 0..2047
            float x = (float)(2 * idx + 1) * (1.0f / (float)L);
            g_ct2[idx] = (2.0f / (float)L) * __fdividef(cospif(x), sinpif(x));
        }
        __syncthreads();
        if (t < 64) {
            float s = 0.0f;
#pragma unroll
            for (int kk = 0; kk < NK; kk++) s += SM[kk * 64 + t];
            const int l = pb * 64 + t;
            g_P[l] = s;
            if (l & 1) g_Po[l >> 1] = s; else g_Pe[l >> 1] = s;
        }
    }

    // ======================= Grid barrier #1 =======================
    __threadfence();
    if (t == 0) {
        int old = atomicAdd(&g_cnt, 1);
        int target = old - (old % NBLK) + NBLK;
        while (*(volatile int*)&g_cnt < target) __nanosleep(64);
    }
    __syncthreads();

    // ======================= Phase 2 =======================
    // h = k-split (0..2), K0/KC per h; p = parity; m0 = 64-l group.
    const int h  = bx >> 7;                        // 0..2
    const int q  = bx & 127;
    const int p  = q >> 6;
    const int m0 = (q & 63) * 64;
    const int K0  = (h == 0) ? 0 : (h == 1 ? 640 : 1408);
    const int KC  = (h == 1) ? 768 : 640;
    const int NIT = KC >> 7;                       // 5 or 6 (4k-subtiles per j)

    // Stage windows of the opposite-parity half of P, plus CT slice:
    //   A(m,k') = S[(m+p+K0+k') & 4095]    -> SA[x], x = mm + k'
    //   B(m,k') = S[(m-K0-k'-1+p) & 4095]  -> SB[y], y = mm - k' + KC-1
    {
        const float* S = p ? g_Pe : g_Po;
        const int baseA = m0 + p + K0;
        const int baseB = m0 + p - K0 - KC + 2 * HALF;  // positive before mask
        const int lim = KC + 64;
        for (int x = t; x < lim; x += 512) {
            SA[x] = S[(baseA + x) & (HALF - 1)];
            SB[x] = S[(baseB + x) & (HALF - 1)];
        }
        for (int x = t; x < KC; x += 512) CTs[x] = g_ct2[K0 + x];
    }
    __syncthreads();

    const int ly = t & 15;              // m = m0 + 4*ly + r   (r in [0,4))
    const int j  = t >> 4;              // 0..31, k' chunk [j*4*NIT, +4*NIT)
    const float4* SA4 = (const float4*)SA;
    const float4* SB4 = (const float4*)SB;
    const float4* CT4 = (const float4*)CTs;

    const int xa0 = ly + j * NIT;              // A float4 base at kt=0
    const int xb0 = (KC >> 2) - 1 + ly - j * NIT;  // B low float4 base at kt=0

    float4 A0 = SA4[xa0];               // a0..a3 for current kt
    float4 B1 = SB4[xb0 + 1];           // b4..b7 for current kt

    float acc0 = 0.f, acc1 = 0.f, acc2 = 0.f, acc3 = 0.f;

#define SUBTILE(kt_)                                                          \
    {                                                                         \
        float4 A1 = SA4[xa0 + (kt_) + 1];                                     \
        float4 B0 = SB4[xb0 - (kt_)];                                         \
        float4 C  = CT4[j * NIT + (kt_)];                                     \
        float a0=A0.x,a1=A0.y,a2=A0.z,a3=A0.w,a4=A1.x,a5=A1.y,a6=A1.z;        \
        float b0=B0.x,b1=B0.y,b2=B0.z,b3=B0.w,b4=B1.x,b5=B1.y,b6=B1.z;        \
        acc0 = fmaf(C.x, a0 - b3, acc0);                                      \
        acc0 = fmaf(C.y, a1 - b2, acc0);                                      \
        acc0 = fmaf(C.z, a2 - b1, acc0);                                      \
        acc0 = fmaf(C.w, a3 - b0, acc0);                                      \
        acc1 = fmaf(C.x, a1 - b4, acc1);                                      \
        acc1 = fmaf(C.y, a2 - b3, acc1);                                      \
        acc1 = fmaf(C.z, a3 - b2, acc1);                                      \
        acc1 = fmaf(C.w, a4 - b1, acc1);                                      \
        acc2 = fmaf(C.x, a2 - b5, acc2);                                      \
        acc2 = fmaf(C.y, a3 - b4, acc2);                                      \
        acc2 = fmaf(C.z, a4 - b3, acc2);                                      \
        acc2 = fmaf(C.w, a5 - b2, acc2);                                      \
        acc3 = fmaf(C.x, a3 - b6, acc3);                                      \
        acc3 = fmaf(C.y, a4 - b5, acc3);                                      \
        acc3 = fmaf(C.z, a5 - b4, acc3);                                      \
        acc3 = fmaf(C.w, a6 - b3, acc3);                                      \
        A0 = A1; B1 = B0;                                                     \
    }

#pragma unroll
    for (int kt = 0; kt < 5; kt++) SUBTILE(kt);
    if (NIT == 6) SUBTILE(5);
#undef SUBTILE

    // lanes 0-15 absorb lanes 16-31 (same ly, j+1)
    acc0 += __shfl_down_sync(0xffffffffu, acc0, 16);
    acc1 += __shfl_down_sync(0xffffffffu, acc1, 16);
    acc2 += __shfl_down_sync(0xffffffffu, acc2, 16);
    acc3 += __shfl_down_sync(0xffffffffu, acc3, 16);

    const int lane = t & 31, w = t >> 5;
    if (lane < 16) {
        float4 v; v.x = acc0; v.y = acc1; v.z = acc2; v.w = acc3;
        ((float4*)(red2 + w * 68))[lane] = v;   // red2[w*68 + 4*ly + r]
    }
    __syncthreads();

    if (t < 64) {
        float s = 0.0f;
#pragma unroll
        for (int w2 = 0; w2 < 16; w2++) s += red2[w2 * 68 + t];
        g_Qp[h][2 * (m0 + t) + p] = s;          // ct2 already carries 2/L
    }

    // ======================= Grid barrier #2 =======================
    __threadfence();
    if (t == 0) {
        int old = atomicAdd(&g_cnt, 1);
        int target = old - (old % NBLK) + NBLK;
        while (*(volatile int*)&g_cnt < target) __nanosleep(64);
    }
    __syncthreads();

    // ======================= Phase 3: combine =======================
    // 131072 float4 outputs; 384*512 = 196608 threads -> gid < 131072 active.
    const int gid = bx * 512 + t;
    if (gid < (NB * L) / 4) {
        const int b  = gid >> 11;                // 2048 float4 per row
        const int l4 = gid & 2047;
        float a = g_pa4[4 * b] + g_pa4[4 * b + 1] + g_pa4[4 * b + 2] + g_pa4[4 * b + 3];
        float c = g_pc4[4 * b] + g_pc4[4 * b + 1] + g_pc4[4 * b + 2] + g_pc4[4 * b + 3];
        float4 P4 = ((const float4*)g_P)[l4];
        float4 q0 = ((const float4*)g_Qp[0])[l4];
        float4 q1 = ((const float4*)g_Qp[1])[l4];
        float4 q2 = ((const float4*)g_Qp[2])[l4];
        float4 o;
        o.x = fmaf(a, P4.x, c * ((q0.x + q1.x) + q2.x));
        o.y = fmaf(a, P4.y, c * ((q0.y + q1.y) + q2.y));
        o.z = fmaf(a, P4.z, c * ((q0.z + q1.z) + q2.z));
        o.w = fmaf(a, P4.w, c * ((q0.w + q1.w) + q2.w));
        ((float4*)out)[gid] = o;
    }
}

// ---------------------------------------------------------------------------
extern "C" void kernel_launch(void* const* d_in, const int* in_sizes, int n_in,
                              void* d_out, int out_size) {
    const float* u   = (const float*)d_in[0];  // (64, 8192)
    const float* ev  = (const float*)d_in[1];  // (32, 8192)
    const float* lam = (const float*)d_in[2];  // (32,)
    float* out = (float*)d_out;                // (64, 8192)

    kfused<<<NBLK, 512>>>(u, ev, lam, out);
}

// round 16
// speedup vs baseline: 1.1881x; 1.1881x over previous
#include <cuda_runtime.h>

// Shapes fixed by the dataset: u (B=64, L=8192), ev (K=32, L), lam (K)
#define L      8192
#define NB     64
#define NK     32
#define HALF   4096   // L/2
#define KD     2048   // number of odd d < L/2
#define NBLK   128    // grid size (all co-resident: 1 block/SM, 128 <= 148)

// Device scratch (no allocs allowed)
__device__ float g_ct2[KD];    // (2/L)*cot(pi*(2k+1)/L)
__device__ float g_P[L];       // P[l] = sum_k lam_k ev[k][l]
__device__ float g_Po[HALF];   // P at odd l
__device__ float g_Pe[HALF];   // P at even l
__device__ float g_pa2[NBLK];  // half-row Re partials
__device__ float g_pc2[NBLK];  // half-row Im partials
__device__ int   g_cnt;        // grid-barrier epoch counter

// ---------------------------------------------------------------------------
// Fused persistent kernel: 128 blocks x 1024 threads, all resident.
// Phase 1 (every block, balanced — R12 best):
//   a/c: block bx -> batch b = bx>>1, half = bx&1 -> g_pa2[bx], g_pc2[bx].
//   P:   block bx -> l in [bx*64, bx*64+64), k-parallel park in smem + reduce.
//   ct2: 16-entry chunk per block.
// Grid barrier (atomic epoch counter + nanosleep spin).
// Phase 2: 4m x 32k rolling register tile with a 1-deep SOFTWARE PIPELINE:
//   subtile kt+1's A/B/C are loaded into prefetch regs before kt's FMA block,
//   hiding the per-subtile LDS arrival latency. CT staged in smem.
__global__ void __launch_bounds__(1024, 1) kfused(const float* __restrict__ u,
                                                  const float* __restrict__ ev,
                                                  const float* __restrict__ lam,
                                                  float* __restrict__ out) {
    __shared__ alignas(16) float SA[2112];
    __shared__ alignas(16) float SB[2120];
    __shared__ alignas(16) float CTs[2048];
    __shared__ alignas(16) float red2[32 * 68];   // also reused as PS in phase 1
    __shared__ float Ps[64], aS[NB], cS[NB], Qs[64];
    __shared__ float wa[32], wc[32];

    const int t  = threadIdx.x;
    const int bx = blockIdx.x;

    // ======================= Phase 1 =======================
    {
        float* PS = red2;                    // 32 x 64 floats (k-major partials)

        // -- issue both global loads early (independent streams) --
        const int b    = bx >> 1;
        const int half = bx & 1;
        const int i    = half * 1024 + t;    // float4 index in u row (2048/row)
        float4 uv = ((const float4*)(u + (size_t)b * L))[i];

        float4 e4;
        const int k  = t >> 4;               // only t<512 used (k<32)
        const int lo = t & 15;
        if (t < 512)
            e4 = ((const float4*)ev)[k * (L / 4) + bx * 16 + lo];

        // -- a/c partial --
        float x1 = (float)(4 * i + 1) * (1.0f / (float)L);
        float x3 = (float)(4 * i + 3) * (1.0f / (float)L);
        float c1 = __fdividef(cospif(x1), sinpif(x1));
        float c3 = __fdividef(cospif(x3), sinpif(x3));
        float a = uv.x + uv.z;
        float c = -(uv.y * c1 + uv.w * c3);
        if (i == 0) a += (float)(L / 2) * uv.x;
#pragma unroll
        for (int off = 16; off > 0; off >>= 1) {
            a += __shfl_down_sync(0xffffffffu, a, off);
            c += __shfl_down_sync(0xffffffffu, c, off);
        }
        const int lane = t & 31, w = t >> 5;
        if (lane == 0) { wa[w] = a; wc[w] = c; }

        // -- P partial: park lam[k]*ev in smem --
        if (t < 512) {
            float lk = __ldg(lam + k);
            float4 v; v.x = lk * e4.x; v.y = lk * e4.y; v.z = lk * e4.z; v.w = lk * e4.w;
            ((float4*)PS)[k * 16 + lo] = v;  // PS[k*64 + 4*lo + comp]
        }
        __syncthreads();

        // -- P reduce: thread q < 64 sums over k, writes l = bx*64 + q --
        if (t < 64) {
            float s = 0.0f;
#pragma unroll
            for (int kk = 0; kk < NK; kk++) s += PS[kk * 64 + t];
            const int l = bx * 64 + t;
            g_P[l] = s;
            if (l & 1) g_Po[l >> 1] = s; else g_Pe[l >> 1] = s;
        } else if (t < 96) {
            // -- a/c final reduce (warp 2, lanes = t-64) --
            float av = wa[t - 64], cv = wc[t - 64];
#pragma unroll
            for (int off = 16; off > 0; off >>= 1) {
                av += __shfl_down_sync(0xffffffffu, av, off);
                cv += __shfl_down_sync(0xffffffffu, cv, off);
            }
            if (t == 64) { g_pa2[bx] = av; g_pc2[bx] = cv; }
        } else if (t < 112) {
            // -- ct2 chunk: idx in [bx*16, bx*16+16) --
            int idx = bx * 16 + (t - 96);
            float x = (float)(2 * idx + 1) * (1.0f / (float)L);
            g_ct2[idx] = (2.0f / (float)L) * __fdividef(cospif(x), sinpif(x));
        }
        __syncthreads();   // red2 reused in phase 2
    }

    // ======================= Grid barrier =======================
    __threadfence();                        // publish phase-1 writes
    if (t == 0) {
        int old = atomicAdd(&g_cnt, 1);
        int target = ((old >> 7) + 1) << 7; // round old+1 up to multiple of 128
        while (*(volatile int*)&g_cnt < target) __nanosleep(64);
    }
    __syncthreads();

    // ======================= Phase 2 =======================
    const int p  = bx >> 6;
    const int m0 = (bx & 63) * 64;

    // Stage shifted copies of the opposite-parity half of P + CT table:
    //   A(m,k) = S[m+k+p]    -> SA[x] = S[(m0+p+x) & 4095],       A = SA[mm+k]
    //   B(m,k) = S[m-k-1+p]  -> SB[y] = S[(m0+p-2052+y) & 4095],  B = SB[mm-k+2051]
    {
        const float* S = p ? g_Pe : g_Po;
        const int baseA = m0 + p;
        const int baseB = m0 + p - 2052 + HALF;   // keep positive before mask
#pragma unroll
        for (int x = t; x < 2112; x += 1024) SA[x] = S[(baseA + x) & (HALF - 1)];
#pragma unroll
        for (int y = t; y < 2120; y += 1024) SB[y] = S[(baseB + y) & (HALF - 1)];
        CTs[t]        = g_ct2[t];
        CTs[t + 1024] = g_ct2[t + 1024];
    }
    if (t < NB) {
        aS[t] = g_pa2[2 * t] + g_pa2[2 * t + 1];
        cS[t] = g_pc2[2 * t] + g_pc2[2 * t + 1];
    } else if (t < NB + 64) {
        int mm = t - NB;
        Ps[mm] = g_P[2 * (m0 + mm) + p];
    }
    __syncthreads();

    const int ly = t & 15;              // m-subtile: m = m0 + 4*ly + r
    const int j  = t >> 4;              // 0..63, k-range [32j, 32j+32)
    const float4* SA4 = (const float4*)SA;
    const float4* SB4 = (const float4*)SB;
    const float4* CT4 = (const float4*)CTs;

    const int xa0 = ly + 8 * j;         // A float4 base at kt=0
    const int xb0 = 512 + ly - 8 * j;   // B low float4 base at kt=0

    // Software pipeline: current regs {A0,A1,B0,B1,C}, prefetch {A1n,B0n,Cn}.
    float4 A0 = SA4[xa0];               // a0..a3
    float4 B1 = SB4[xb0 + 1];           // b4..b7
    float4 A1 = SA4[xa0 + 1];           // a4..a7 (kt=0)
    float4 B0 = SB4[xb0];               // b0..b3 (kt=0)
    float4 C  = CT4[8 * j];             // coefficients (kt=0)

    float acc0 = 0.f, acc1 = 0.f, acc2 = 0.f, acc3 = 0.f;
#pragma unroll
    for (int kt = 0; kt < 8; kt++) {
        float4 A1n, B0n, Cn;
        if (kt < 7) {                   // prefetch kt+1 BEFORE kt's math
            A1n = SA4[xa0 + kt + 2];
            B0n = SB4[xb0 - kt - 1];
            Cn  = CT4[8 * j + kt + 1];
        }
        float a0 = A0.x, a1 = A0.y, a2 = A0.z, a3 = A0.w;
        float a4 = A1.x, a5 = A1.y, a6 = A1.z;
        float b0 = B0.x, b1 = B0.y, b2 = B0.z, b3 = B0.w;
        float b4 = B1.x, b5 = B1.y, b6 = B1.z;
        // acc[r] += C[s] * (a[r+s] - b[3+r-s])
        acc0 = fmaf(C.x, a0 - b3, acc0);
        acc0 = fmaf(C.y, a1 - b2, acc0);
        acc0 = fmaf(C.z, a2 - b1, acc0);
        acc0 = fmaf(C.w, a3 - b0, acc0);
        acc1 = fmaf(C.x, a1 - b4, acc1);
        acc1 = fmaf(C.y, a2 - b3, acc1);
        acc1 = fmaf(C.z, a3 - b2, acc1);
        acc1 = fmaf(C.w, a4 - b1, acc1);
        acc2 = fmaf(C.x, a2 - b5, acc2);
        acc2 = fmaf(C.y, a3 - b4, acc2);
        acc2 = fmaf(C.z, a4 - b3, acc2);
        acc2 = fmaf(C.w, a5 - b2, acc2);
        acc3 = fmaf(C.x, a3 - b6, acc3);
        acc3 = fmaf(C.y, a4 - b5, acc3);
        acc3 = fmaf(C.z, a5 - b4, acc3);
        acc3 = fmaf(C.w, a6 - b3, acc3);
        A0 = A1; B1 = B0;               // rolling windows
        A1 = A1n; B0 = B0n; C = Cn;     // consume prefetch
    }

    // Lanes 0-15 of each warp absorb lanes 16-31 (same ly, j+1).
    acc0 += __shfl_down_sync(0xffffffffu, acc0, 16);
    acc1 += __shfl_down_sync(0xffffffffu, acc1, 16);
    acc2 += __shfl_down_sync(0xffffffffu, acc2, 16);
    acc3 += __shfl_down_sync(0xffffffffu, acc3, 16);

    const int lane = t & 31, w = t >> 5;
    if (lane < 16) {
        float4 v; v.x = acc0; v.y = acc1; v.z = acc2; v.w = acc3;
        ((float4*)(red2 + w * 68))[lane] = v;     // red2[w*68 + 4*ly + r]
    }
    __syncthreads();

    if (t < 64) {
        float s = 0.0f;
#pragma unroll
        for (int w2 = 0; w2 < 32; w2++) s += red2[w2 * 68 + t];
        Qs[t] = s;                       // ct2 already carries 2/L
    }
    __syncthreads();

    // 64 b x 64 m outputs, 4 per thread
#pragma unroll
    for (int r = 0; r < 4; r++) {
        int idx = r * 1024 + t;
        int b   = idx >> 6;
        int mm  = idx & 63;
        out[(size_t)b * L + 2 * (m0 + mm) + p] =
            fmaf(aS[b], Ps[mm], cS[b] * Qs[mm]);
    }
}

// ---------------------------------------------------------------------------
extern "C" void kernel_launch(void* const* d_in, const int* in_sizes, int n_in,
                              void* d_out, int out_size) {
    const float* u   = (const float*)d_in[0];  // (64, 8192)
    const float* ev  = (const float*)d_in[1];  // (32, 8192)
    const float* lam = (const float*)d_in[2];  // (32,)
    float* out = (float*)d_out;                // (64, 8192)

    kfused<<<NBLK, 1024>>>(u, ev, lam, out);
}